// round 12
// baseline (speedup 1.0000x reference)
#include <cuda_runtime.h>

#define BB 4
#define NN 16384
#define SSZ 2048            // queries per batch (NEVENT)
#define DD 62
#define CC 64               // D + 2
#define KK 64               // NSAMPLE
#define NQ (BB*SSZ)         // 8192 total queries
#define MMM 8388608         // SSZ*KK*CC per batch
#define R2 0.01f

// ---- scratch (device globals; deterministic: fully overwritten per launch) ----
__device__ int    g_idx[NQ*KK];     // neighbor indices
__device__ float4 g_mean4[NQ*16];   // per-(query,channel) means
__device__ float  g_ss[NQ];         // per-query sum of squared centered
__device__ float  g_rstd[BB];       // 1/(std+1e-5) per batch
__device__ float  g_pn[BB*NN];      // precomputed |p|^2 (exact ref op order)
__device__ int    g_done;           // last-block counter; self-resets each launch

// ---------------------------------------------------------------------------
// K_PN: |p|^2 for every point, replicating the reference op sequence exactly:
// pn = add(mul(x,x), mul(y,y)). xy is (B,N,2) contiguous -> float2 index = i.
// ---------------------------------------------------------------------------
__global__ __launch_bounds__(256) void k_pn(const float* __restrict__ xy)
{
    int i = blockIdx.x * 256 + threadIdx.x;   // 0 .. BB*NN-1
    float2 p = reinterpret_cast<const float2*>(xy)[i];
    g_pn[i] = __fadd_rn(__fmul_rn(p.x, p.x), __fmul_rn(p.y, p.y));
}

// ---------------------------------------------------------------------------
// K_A: fused ball-query + stats + (last block) finalize.
// ONE query per 32-thread CTA, grid 8192 > 4736 concurrent CTAs => ~1.7
// waves; the HW scheduler refills SMs as short queries retire (R11 win).
//
// Distance: reference computes d = (qn + pn) - 2*c with each op rounded.
// 2*c is an EXACT doubling, so fmaf(-2, c, e) == fsub(e, 2*c) bit-for-bit
// (single rounding either way) -> fused, exact. pn comes precomputed from
// g_pn (identical op sequence). c = fma(qy,py, qx*px) as before.
//
// Stats: lane = channel pair; fixed-order shfl reduction (deterministic).
// Finalize: last CTA (atomic counter) reduces g_ss -> g_rstd in a fixed
// order independent of which block runs it, then resets the counter.
// ---------------------------------------------------------------------------
__global__ void __launch_bounds__(32) k_search_stats(
    const float* __restrict__ xy, const float* __restrict__ ev,
    const int* __restrict__ fps, float* __restrict__ out_xy, int write_xy)
{
    int lane = threadIdx.x;
    unsigned lmask = (1u << lane) - 1u;
    int q = blockIdx.x;
    int b = q >> 11;                          // q / SSZ

    __shared__ int sidx[KK];

    const float2* xyb  = reinterpret_cast<const float2*>(xy) + (size_t)b * NN;
    const float4* xyb4 = reinterpret_cast<const float4*>(xyb);
    const float4* pnb4 = reinterpret_cast<const float4*>(g_pn + (size_t)b * NN);

    float2 qp = xyb[fps[q]];
    float qn = __fadd_rn(__fmul_rn(qp.x, qp.x), __fmul_rn(qp.y, qp.y));
    if (write_xy && lane == 0) {
        out_xy[2*q] = qp.x; out_xy[2*q+1] = qp.y;
    }

    // ---- search: 128 candidates per iteration, pipelined loads ----
    int cnt = 0;                              // warp-uniform
    float4 fa = xyb4[2*lane];
    float4 fb = xyb4[2*lane + 1];
    float4 fp = pnb4[lane];
    for (int j0 = 0; ; j0 += 128) {
        int jn = j0 + 128;
        bool more = (jn < NN);
        float4 na, nb, np;                    // prefetch next chunk
        if (more) {
            na = xyb4[(jn >> 1) + 2*lane];
            nb = xyb4[(jn >> 1) + 2*lane + 1];
            np = pnb4[(jn >> 2) + lane];
        }
        float c0 = __fmaf_rn(qp.y, fa.y, __fmul_rn(qp.x, fa.x));
        float e0 = __fadd_rn(qn, fp.x);
        bool  h0 = !(__fmaf_rn(-2.0f, c0, e0) > R2);
        float c1 = __fmaf_rn(qp.y, fa.w, __fmul_rn(qp.x, fa.z));
        float e1 = __fadd_rn(qn, fp.y);
        bool  h1 = !(__fmaf_rn(-2.0f, c1, e1) > R2);
        float c2 = __fmaf_rn(qp.y, fb.y, __fmul_rn(qp.x, fb.x));
        float e2 = __fadd_rn(qn, fp.z);
        bool  h2 = !(__fmaf_rn(-2.0f, c2, e2) > R2);
        float c3 = __fmaf_rn(qp.y, fb.w, __fmul_rn(qp.x, fb.z));
        float e3 = __fadd_rn(qn, fp.w);
        bool  h3 = !(__fmaf_rn(-2.0f, c3, e3) > R2);

        unsigned m0 = __ballot_sync(0xffffffffu, h0);
        unsigned m1 = __ballot_sync(0xffffffffu, h1);
        unsigned m2 = __ballot_sync(0xffffffffu, h2);
        unsigned m3 = __ballot_sync(0xffffffffu, h3);

        int pos = cnt + __popc(m0 & lmask) + __popc(m1 & lmask)
                      + __popc(m2 & lmask) + __popc(m3 & lmask);
        int base = j0 + 4*lane;
        if (h0 && pos < KK) sidx[pos] = base;
        pos += h0 ? 1 : 0;
        if (h1 && pos < KK) sidx[pos] = base + 1;
        pos += h1 ? 1 : 0;
        if (h2 && pos < KK) sidx[pos] = base + 2;
        pos += h2 ? 1 : 0;
        if (h3 && pos < KK) sidx[pos] = base + 3;

        cnt += __popc(m0) + __popc(m1) + __popc(m2) + __popc(m3);
        if (cnt >= KK || !more) break;
        fa = na; fb = nb; fp = np;
    }
    __syncwarp();
    if (cnt < KK) {                            // pad with first hit (cnt>=1: self)
        int f0 = sidx[0];
        for (int p = cnt + lane; p < KK; p += 32) sidx[p] = f0;
        __syncwarp();
    }

    // persist indices for k_write (coalesced 256B per warp)
    g_idx[(size_t)q * KK + lane]      = sidx[lane];
    g_idx[(size_t)q * KK + lane + 32] = sidx[lane + 32];

    // ---- stats: lane = channel pair ----
    const float2* evb2 = reinterpret_cast<const float2*>(ev + (size_t)b * NN * DD);
    float2 s1 = make_float2(0.f,0.f), s2 = make_float2(0.f,0.f);
    bool isxy = (lane == 31);
    #pragma unroll 8
    for (int k = 0; k < KK; k++) {
        int j = sidx[k];                       // LDS broadcast
        float2 v = isxy ? xyb[j] : evb2[(size_t)j * 31 + lane];
        s1.x += v.x; s1.y += v.y;
        s2.x = fmaf(v.x, v.x, s2.x);
        s2.y = fmaf(v.y, v.y, s2.y);
    }
    float2 m = make_float2(s1.x * (1.0f/64.0f), s1.y * (1.0f/64.0f));
    reinterpret_cast<float2*>(g_mean4)[(size_t)q * 32 + lane] = m;
    float ss = (s2.x - s1.x * m.x) + (s2.y - s1.y * m.y);
    #pragma unroll
    for (int off = 16; off >= 1; off >>= 1)
        ss += __shfl_down_sync(0xffffffffu, ss, off);
    if (lane == 0) g_ss[q] = ss;

    // ---- last-block finalize: g_ss -> g_rstd (fixed order, deterministic) ----
    __threadfence();
    int old = 0;
    if (lane == 0) old = atomicAdd(&g_done, 1);
    old = __shfl_sync(0xffffffffu, old, 0);
    if (old == NQ - 1) {
        __threadfence();                       // all g_ss writes visible
        #pragma unroll
        for (int bb = 0; bb < BB; bb++) {
            float s = 0.f;
            #pragma unroll
            for (int i = 0; i < SSZ/32; i++)   // lane-strided, fixed order
                s += g_ss[(size_t)bb * SSZ + i * 32 + lane];
            #pragma unroll
            for (int off = 16; off >= 1; off >>= 1)
                s += __shfl_down_sync(0xffffffffu, s, off);
            if (lane == 0) {
                float var = s / (float)(MMM - 1);   // ddof = 1
                g_rstd[bb] = 1.0f / (sqrtf(var) + 1e-5f);
            }
        }
        if (lane == 0) g_done = 0;             // reset for next graph replay
    }
}

// ---------------------------------------------------------------------------
// K_C: regather + normalize + affine. Block per query; WARP per k-row:
// lane = channel pair (31 event pairs + 1 xy pair) -> one 248B gather region
// and one coalesced 256B store per row. 8 rows per warp, unrolled.
// ---------------------------------------------------------------------------
__global__ __launch_bounds__(256) void k_write(
    const float* __restrict__ xy, const float* __restrict__ ev,
    const float* __restrict__ alpha, const float* __restrict__ beta,
    float* __restrict__ out_ev)
{
    int q = blockIdx.x;
    int b = q >> 11;
    int w = threadIdx.x >> 5, lane = threadIdx.x & 31;

    __shared__ int sidx[KK];
    if (threadIdx.x < KK) sidx[threadIdx.x] = g_idx[(size_t)q * KK + threadIdx.x];
    __syncthreads();

    float  rstd = g_rstd[b];
    float2 mean = reinterpret_cast<const float2*>(g_mean4)[(size_t)q * 32 + lane];
    float2 al   = reinterpret_cast<const float2*>(alpha)[lane];
    float2 be   = reinterpret_cast<const float2*>(beta)[lane];

    const float2* evb2 = reinterpret_cast<const float2*>(ev + (size_t)b * NN * DD);
    const float2* xyb  = reinterpret_cast<const float2*>(xy) + (size_t)b * NN;
    float2* op = reinterpret_cast<float2*>(out_ev) + (size_t)q * KK * 32;

    bool isxy = (lane == 31);
    #pragma unroll
    for (int ki = 0; ki < 8; ki++) {
        int k = ki * 8 + w;
        int j = sidx[k];
        float2 v = isxy ? xyb[j] : evb2[(size_t)j * 31 + lane];
        float2 r;
        r.x = fmaf(al.x, (v.x - mean.x) * rstd, be.x);
        r.y = fmaf(al.y, (v.y - mean.y) * rstd, be.y);
        op[(size_t)k * 32 + lane] = r;
    }
}

// ---------------------------------------------------------------------------
extern "C" void kernel_launch(void* const* d_in, const int* in_sizes, int n_in,
                              void* d_out, int out_size)
{
    const float* xy    = (const float*)d_in[0];
    const float* ev    = (const float*)d_in[1];
    const int*   fps   = (const int*)d_in[2];
    const float* alpha = (const float*)d_in[3];
    const float* beta  = (const float*)d_in[4];
    float* out = (float*)d_out;

    long long ev_elems = (long long)NQ * KK * CC;
    int has_xy = ((long long)out_size >= ev_elems + (long long)NQ * 2) ? 1 : 0;
    float* out_ev = out + (has_xy ? NQ * 2 : 0);

    k_pn          <<<(BB*NN)/256, 256>>>(xy);
    k_search_stats<<<NQ, 32>>>(xy, ev, fps, out, has_xy);   // 1 query / CTA
    k_write       <<<NQ, 256>>>(xy, ev, alpha, beta, out_ev);
}

// round 13
// speedup vs baseline: 1.1277x; 1.1277x over previous
#include <cuda_runtime.h>

#define BB 4
#define NN 16384
#define SSZ 2048            // queries per batch (NEVENT)
#define DD 62
#define CC 64               // D + 2
#define KK 64               // NSAMPLE
#define NQ (BB*SSZ)         // 8192 total queries
#define MMM 8388608         // SSZ*KK*CC per batch
#define R2 0.01f

// ---- scratch (device globals; deterministic: fully overwritten per launch) ----
__device__ int    g_idx[NQ*KK];     // neighbor indices
__device__ float4 g_mean4[NQ*16];   // per-(query,channel) means
__device__ float  g_ss[NQ];         // per-query sum of squared centered
__device__ float  g_rstd[BB];       // 1/(std+1e-5) per batch

// ---------------------------------------------------------------------------
// K_A: fused ball-query + stats. ONE query per 32-thread CTA, grid 8192.
// 8192 blocks > 4736 concurrent CTAs (148 SM x 32) => ~1.7 waves; the HW
// block scheduler refills SMs as short (interior) queries retire, which is
// what balances the ragged scan lengths (R11 win — do not re-structure).
//
// Distance per reference, with ONE exact fusion (validated R12: rel_err
// bit-identical): reference d = (qn + pn) - 2*c; since 2*c is an exact
// doubling, fmaf(-2, c, qn+pn) == fsub(qn+pn, 2*c) bit-for-bit.
//   pn = add(mul(x,x), mul(y,y))   (no contraction — matches ref)
//   c  = fma(qy,py, qx*px)         (einsum K-ascending chain)
//   hit iff !(fmaf(-2,c, qn+pn) > R^2)
//
// Stats: lane = channel pair; fixed-order shfl reduction (deterministic).
// ---------------------------------------------------------------------------
__global__ void __launch_bounds__(32) k_search_stats(
    const float* __restrict__ xy, const float* __restrict__ ev,
    const int* __restrict__ fps, float* __restrict__ out_xy, int write_xy)
{
    int lane = threadIdx.x;
    unsigned lmask = (1u << lane) - 1u;
    int q = blockIdx.x;
    int b = q >> 11;                          // q / SSZ

    __shared__ int sidx[KK];

    const float2* xyb  = reinterpret_cast<const float2*>(xy) + (size_t)b * NN;
    const float4* xyb4 = reinterpret_cast<const float4*>(xyb);

    float2 qp = xyb[fps[q]];
    float qn = __fadd_rn(__fmul_rn(qp.x, qp.x), __fmul_rn(qp.y, qp.y));
    if (write_xy && lane == 0) {
        out_xy[2*q] = qp.x; out_xy[2*q+1] = qp.y;
    }

    // ---- search: 128 candidates per iteration, pipelined loads ----
    int cnt = 0;                              // warp-uniform
    float4 fa = xyb4[2*lane];
    float4 fb = xyb4[2*lane + 1];
    for (int j0 = 0; ; j0 += 128) {
        int jn = j0 + 128;
        bool more = (jn < NN);
        float4 na, nb;                        // prefetch next chunk
        if (more) {
            na = xyb4[(jn >> 1) + 2*lane];
            nb = xyb4[(jn >> 1) + 2*lane + 1];
        }
        float pn0 = __fadd_rn(__fmul_rn(fa.x, fa.x), __fmul_rn(fa.y, fa.y));
        float c0  = __fmaf_rn(qp.y, fa.y, __fmul_rn(qp.x, fa.x));
        bool  h0  = !(__fmaf_rn(-2.0f, c0, __fadd_rn(qn, pn0)) > R2);
        float pn1 = __fadd_rn(__fmul_rn(fa.z, fa.z), __fmul_rn(fa.w, fa.w));
        float c1  = __fmaf_rn(qp.y, fa.w, __fmul_rn(qp.x, fa.z));
        bool  h1  = !(__fmaf_rn(-2.0f, c1, __fadd_rn(qn, pn1)) > R2);
        float pn2 = __fadd_rn(__fmul_rn(fb.x, fb.x), __fmul_rn(fb.y, fb.y));
        float c2  = __fmaf_rn(qp.y, fb.y, __fmul_rn(qp.x, fb.x));
        bool  h2  = !(__fmaf_rn(-2.0f, c2, __fadd_rn(qn, pn2)) > R2);
        float pn3 = __fadd_rn(__fmul_rn(fb.z, fb.z), __fmul_rn(fb.w, fb.w));
        float c3  = __fmaf_rn(qp.y, fb.w, __fmul_rn(qp.x, fb.z));
        bool  h3  = !(__fmaf_rn(-2.0f, c3, __fadd_rn(qn, pn3)) > R2);

        unsigned m0 = __ballot_sync(0xffffffffu, h0);
        unsigned m1 = __ballot_sync(0xffffffffu, h1);
        unsigned m2 = __ballot_sync(0xffffffffu, h2);
        unsigned m3 = __ballot_sync(0xffffffffu, h3);

        int pos = cnt + __popc(m0 & lmask) + __popc(m1 & lmask)
                      + __popc(m2 & lmask) + __popc(m3 & lmask);
        int base = j0 + 4*lane;
        if (h0 && pos < KK) sidx[pos] = base;
        pos += h0 ? 1 : 0;
        if (h1 && pos < KK) sidx[pos] = base + 1;
        pos += h1 ? 1 : 0;
        if (h2 && pos < KK) sidx[pos] = base + 2;
        pos += h2 ? 1 : 0;
        if (h3 && pos < KK) sidx[pos] = base + 3;

        cnt += __popc(m0) + __popc(m1) + __popc(m2) + __popc(m3);
        if (cnt >= KK || !more) break;
        fa = na; fb = nb;
    }
    __syncwarp();
    if (cnt < KK) {                            // pad with first hit (cnt>=1: self)
        int f0 = sidx[0];
        for (int p = cnt + lane; p < KK; p += 32) sidx[p] = f0;
        __syncwarp();
    }

    // persist indices for k_write (coalesced 256B per warp)
    g_idx[(size_t)q * KK + lane]      = sidx[lane];
    g_idx[(size_t)q * KK + lane + 32] = sidx[lane + 32];

    // ---- stats: lane = channel pair ----
    const float2* evb2 = reinterpret_cast<const float2*>(ev + (size_t)b * NN * DD);
    float2 s1 = make_float2(0.f,0.f), s2 = make_float2(0.f,0.f);
    bool isxy = (lane == 31);
    #pragma unroll 8
    for (int k = 0; k < KK; k++) {
        int j = sidx[k];                       // LDS broadcast
        float2 v = isxy ? xyb[j] : evb2[(size_t)j * 31 + lane];
        s1.x += v.x; s1.y += v.y;
        s2.x = fmaf(v.x, v.x, s2.x);
        s2.y = fmaf(v.y, v.y, s2.y);
    }
    float2 m = make_float2(s1.x * (1.0f/64.0f), s1.y * (1.0f/64.0f));
    reinterpret_cast<float2*>(g_mean4)[(size_t)q * 32 + lane] = m;
    float ss = (s2.x - s1.x * m.x) + (s2.y - s1.y * m.y);
    #pragma unroll
    for (int off = 16; off >= 1; off >>= 1)
        ss += __shfl_down_sync(0xffffffffu, ss, off);
    if (lane == 0) g_ss[q] = ss;
}

// ---------------------------------------------------------------------------
// K_B: per-batch SS reduce -> rstd. One block per batch, fixed-order tree.
// ---------------------------------------------------------------------------
__global__ __launch_bounds__(256) void k_finalize()
{
    int b = blockIdx.x, t = threadIdx.x;
    __shared__ float sh[256];
    float s = 0.f;
    #pragma unroll
    for (int i = 0; i < 8; i++) s += g_ss[(size_t)b * SSZ + t*8 + i];
    sh[t] = s;
    __syncthreads();
    for (int off = 128; off >= 1; off >>= 1) {
        if (t < off) sh[t] += sh[t + off];
        __syncthreads();
    }
    if (t == 0) {
        float var = sh[0] / (float)(MMM - 1);   // ddof = 1
        g_rstd[b] = 1.0f / (sqrtf(var) + 1e-5f);
    }
}

// ---------------------------------------------------------------------------
// K_C: regather + normalize + affine. Block per query; WARP per k-row:
// lane = channel pair (31 event pairs + 1 xy pair) -> one 248B gather region
// and one coalesced 256B store per row. 8 rows per warp, unrolled.
// ---------------------------------------------------------------------------
__global__ __launch_bounds__(256) void k_write(
    const float* __restrict__ xy, const float* __restrict__ ev,
    const float* __restrict__ alpha, const float* __restrict__ beta,
    float* __restrict__ out_ev)
{
    int q = blockIdx.x;
    int b = q >> 11;
    int w = threadIdx.x >> 5, lane = threadIdx.x & 31;

    __shared__ int sidx[KK];
    if (threadIdx.x < KK) sidx[threadIdx.x] = g_idx[(size_t)q * KK + threadIdx.x];
    __syncthreads();

    float  rstd = g_rstd[b];
    float2 mean = reinterpret_cast<const float2*>(g_mean4)[(size_t)q * 32 + lane];
    float2 al   = reinterpret_cast<const float2*>(alpha)[lane];
    float2 be   = reinterpret_cast<const float2*>(beta)[lane];

    const float2* evb2 = reinterpret_cast<const float2*>(ev + (size_t)b * NN * DD);
    const float2* xyb  = reinterpret_cast<const float2*>(xy) + (size_t)b * NN;
    float2* op = reinterpret_cast<float2*>(out_ev) + (size_t)q * KK * 32;

    bool isxy = (lane == 31);
    #pragma unroll
    for (int ki = 0; ki < 8; ki++) {
        int k = ki * 8 + w;
        int j = sidx[k];
        float2 v = isxy ? xyb[j] : evb2[(size_t)j * 31 + lane];
        float2 r;
        r.x = fmaf(al.x, (v.x - mean.x) * rstd, be.x);
        r.y = fmaf(al.y, (v.y - mean.y) * rstd, be.y);
        op[(size_t)k * 32 + lane] = r;
    }
}

// ---------------------------------------------------------------------------
extern "C" void kernel_launch(void* const* d_in, const int* in_sizes, int n_in,
                              void* d_out, int out_size)
{
    const float* xy    = (const float*)d_in[0];
    const float* ev    = (const float*)d_in[1];
    const int*   fps   = (const int*)d_in[2];
    const float* alpha = (const float*)d_in[3];
    const float* beta  = (const float*)d_in[4];
    float* out = (float*)d_out;

    long long ev_elems = (long long)NQ * KK * CC;
    int has_xy = ((long long)out_size >= ev_elems + (long long)NQ * 2) ? 1 : 0;
    float* out_ev = out + (has_xy ? NQ * 2 : 0);

    k_search_stats<<<NQ, 32>>>(xy, ev, fps, out, has_xy);   // 1 query / CTA
    k_finalize    <<<BB, 256>>>();
    k_write       <<<NQ, 256>>>(xy, ev, alpha, beta, out_ev);
}